// round 7
// baseline (speedup 1.0000x reference)
#include <cuda_runtime.h>
#include <math.h>

// Problem constants
#define NGV    256          // graph-views = 128 graphs x 2 views
#define NNODE  256
#define DFEAT  128
#define KBINS  16
#define ROWP4  33           // padded row length in float4 (132 floats) -> conflict-free LDS.128
#define SMEM_BYTES ((NNODE*ROWP4*4 + 256 + 256 + 128) * 4)

// Scratch (static device globals — no runtime allocation)
__device__ float g_D[(size_t)NGV * NNODE * NNODE];   // 64MB pairwise distances
__device__ float g_sig[NGV * KBINS];                 // per-graph-view signatures
__device__ float g_ntx;                              // NT-Xent loss

__device__ __forceinline__ float ex2f(float x) {
    float r; asm("ex2.approx.f32 %0, %1;" : "=f"(r) : "f"(x)); return r;
}

__global__ __launch_bounds__(256, 1)
void k_main(const float* __restrict__ H1, const float* __restrict__ H2,
            const float* __restrict__ Z1, const float* __restrict__ Z2)
{
    extern __shared__ float sh[];
    float4* sh4  = (float4*)sh;                  // [256][33] float4 (padded rows)
    float*  sq   = sh + NNODE * ROWP4 * 4;       // 256 squared norms
    float*  red  = sq + 256;                     // 256 reduction scratch
    float*  hred = red + 256;                    // 8 warps x 16 hist partials

    const int t = threadIdx.x;
    const int b = blockIdx.x;

    if (b < NGV) {
        // ---------------- graph-view block ----------------
        const float* H = ((b & 1) ? H2 : H1) + (size_t)(b >> 1) * (NNODE * DFEAT);
        const float4* Hv = (const float4*)H;

        // Load H (256x128 f32) into padded shared. Coalesced global, conflict-free shared.
        #pragma unroll
        for (int k = 0; k < 32; ++k) {
            int idx = k * 256 + t;                   // 8192 float4 total
            sh4[(idx >> 5) * ROWP4 + (idx & 31)] = Hv[idx];
        }
        __syncthreads();

        // Squared norms (thread t -> row t)
        {
            float s = 0.f;
            #pragma unroll 8
            for (int d4 = 0; d4 < 32; ++d4) {
                float4 v = sh4[t * ROWP4 + d4];
                s += v.x*v.x + v.y*v.y + v.z*v.z + v.w*v.w;
            }
            sq[t] = s;
        }
        __syncthreads();

        // Pass 1: Gram -> D, accumulate sum(D). Thread tile: 4 rows x 64 cols.
        // rows {ig, ig+64, ig+128, ig+192} (stride-64 keeps own-row LDS.128 conflict-free),
        // cols [jh*64, jh*64+64). j-operand loads are warp-uniform broadcasts.
        const int ig = t & 63;
        const int jh = t >> 6;
        float4* gD4 = (float4*)(g_D + (size_t)b * (NNODE * NNODE));

        float sqi[4];
        #pragma unroll
        for (int r = 0; r < 4; ++r) sqi[r] = sq[ig + 64 * r];

        float sumD = 0.f;
        for (int jt = 0; jt < 4; ++jt) {
            const int j0 = jh * 64 + jt * 16;
            float acc[4][16];
            #pragma unroll
            for (int r = 0; r < 4; ++r)
                #pragma unroll
                for (int u = 0; u < 16; ++u) acc[r][u] = 0.f;

            for (int d4 = 0; d4 < 32; ++d4) {
                float4 a0 = sh4[(ig      ) * ROWP4 + d4];
                float4 a1 = sh4[(ig +  64) * ROWP4 + d4];
                float4 a2 = sh4[(ig + 128) * ROWP4 + d4];
                float4 a3 = sh4[(ig + 192) * ROWP4 + d4];
                #pragma unroll
                for (int u = 0; u < 16; ++u) {
                    float4 bb = sh4[(j0 + u) * ROWP4 + d4];
                    acc[0][u] += a0.x*bb.x + a0.y*bb.y + a0.z*bb.z + a0.w*bb.w;
                    acc[1][u] += a1.x*bb.x + a1.y*bb.y + a1.z*bb.z + a1.w*bb.w;
                    acc[2][u] += a2.x*bb.x + a2.y*bb.y + a2.z*bb.z + a2.w*bb.w;
                    acc[3][u] += a3.x*bb.x + a3.y*bb.y + a3.z*bb.z + a3.w*bb.w;
                }
            }
            // Epilogue: D = sqrt(max(d2,0)+1e-12), store, accumulate sum
            #pragma unroll
            for (int r = 0; r < 4; ++r) {
                const int row = ig + 64 * r;
                #pragma unroll
                for (int u4 = 0; u4 < 4; ++u4) {
                    float4 dv;
                    float* dp = (float*)&dv;
                    #pragma unroll
                    for (int c = 0; c < 4; ++c) {
                        const int u = u4 * 4 + c;
                        float d2 = sqi[r] + sq[j0 + u] - 2.f * acc[r][u];
                        float x  = fmaxf(d2, 0.f) + 1e-12f;
                        float dd = x * rsqrtf(x);          // sqrt via MUFU.RSQ
                        dp[c] = dd;
                        sumD += dd;
                    }
                    gD4[row * 64 + (j0 >> 2) + u4] = dv;
                }
            }
        }

        // Block reduce sum(D) (deterministic tree)
        red[t] = sumD;
        __syncthreads();
        for (int s = 128; s > 0; s >>= 1) {
            if (t < s) red[t] += red[t + s];
            __syncthreads();
        }
        const float invMean = 1.f / (red[0] * (1.f / 65536.f) + 1e-8f);
        __syncthreads();   // protect red[] before reuse below

        // Pass 2: soft histogram. Linear coalesced re-read of D (order-independent sum).
        float hist[KBINS];
        #pragma unroll
        for (int k = 0; k < KBINS; ++k) hist[k] = 0.f;
        const float C2 = -(0.5f / (0.1875f * 0.1875f)) * 1.4426950408889634f; // base-2 exponent coeff

        for (int k = 0; k < 64; ++k) {
            float4 dv = gD4[k * 256 + t];
            float dd[4] = {dv.x, dv.y, dv.z, dv.w};
            #pragma unroll
            for (int c = 0; c < 4; ++c) {
                float dn = dd[c] * invMean;
                #pragma unroll
                for (int kk = 0; kk < KBINS; ++kk) {
                    float tt = dn - 0.2f * (float)kk;
                    hist[kk] += ex2f(C2 * tt * tt);
                }
            }
        }

        // Hist reduction: warp shuffle -> shared -> 16 threads
        {
            const int wid = t >> 5, lane = t & 31;
            #pragma unroll
            for (int kk = 0; kk < KBINS; ++kk) {
                float v = hist[kk];
                #pragma unroll
                for (int off = 16; off; off >>= 1) v += __shfl_down_sync(0xffffffffu, v, off);
                if (lane == 0) hred[wid * KBINS + kk] = v;
            }
            __syncthreads();
            if (t < KBINS) {
                float v = 0.f;
                #pragma unroll
                for (int w = 0; w < 8; ++w) v += hred[w * KBINS + t];
                red[t] = v;
            }
            __syncthreads();
            if (t < KBINS) {
                float tot = 0.f;
                #pragma unroll
                for (int kk = 0; kk < KBINS; ++kk) tot += red[kk];
                g_sig[b * KBINS + t] = red[t] / (tot + 1e-8f);
            }
        }
    } else {
        // ---------------- NT-Xent block (b == 256) ----------------
        // Load z = [z1; z2] (256 x 128) into padded shared
        #pragma unroll
        for (int k = 0; k < 32; ++k) {
            int idx = k * 256 + t;
            int row = idx >> 5, d4 = idx & 31;
            const float4* Z = (row < 128) ? ((const float4*)Z1 + row * 32)
                                          : ((const float4*)Z2 + (row - 128) * 32);
            sh4[row * ROWP4 + d4] = Z[d4];
        }
        __syncthreads();

        // Row-normalize in place: z / (||z|| + eps)
        {
            float ssum = 0.f;
            #pragma unroll 8
            for (int d4 = 0; d4 < 32; ++d4) {
                float4 v = sh4[t * ROWP4 + d4];
                ssum += v.x*v.x + v.y*v.y + v.z*v.z + v.w*v.w;
            }
            float nrm = ssum * rsqrtf(fmaxf(ssum, 1e-30f));
            float rn = 1.f / (nrm + 1e-8f);
            #pragma unroll 8
            for (int d4 = 0; d4 < 32; ++d4) {
                float4 v = sh4[t * ROWP4 + d4];
                v.x *= rn; v.y *= rn; v.z *= rn; v.w *= rn;
                sh4[t * ROWP4 + d4] = v;
            }
        }
        __syncthreads();

        // Thread t owns sim row t; streaming (online) logsumexp over 16-col tiles.
        const int lab = (t + 128) & 255;
        float m = -INFINITY, s = 0.f, num = 0.f;
        const float L2E = 1.4426950408889634f;

        for (int jt = 0; jt < 16; ++jt) {
            const int j0 = jt * 16;
            float acc[16];
            #pragma unroll
            for (int u = 0; u < 16; ++u) acc[u] = 0.f;
            for (int d4 = 0; d4 < 32; ++d4) {
                float4 a = sh4[t * ROWP4 + d4];
                #pragma unroll
                for (int u = 0; u < 16; ++u) {
                    float4 bb = sh4[(j0 + u) * ROWP4 + d4];
                    acc[u] += a.x*bb.x + a.y*bb.y + a.z*bb.z + a.w*bb.w;
                }
            }
            #pragma unroll
            for (int u = 0; u < 16; ++u) {
                const int j = j0 + u;
                float v = 2.f * acc[u];          // / TEMP (0.5)
                if (j == t)   v = -1e9f;         // diag mask
                if (j == lab) num = v;           // positive pair logit
                float nm = fmaxf(m, v);
                s = s * ex2f((m - nm) * L2E) + ex2f((v - nm) * L2E);
                m = nm;
            }
        }
        float li = (m + logf(s)) - num;          // logsumexp - sim[i, label]
        red[t] = li;
        __syncthreads();
        for (int st = 128; st > 0; st >>= 1) {
            if (t < st) red[t] += red[t + st];
            __syncthreads();
        }
        if (t == 0) g_ntx = red[0] * (1.f / 256.f);
    }
}

__global__ void k_final(float* __restrict__ out, int out_size)
{
    __shared__ float red[128];
    const int t = threadIdx.x;   // 128 threads, t = graph index
    float v = 0.f;
    #pragma unroll
    for (int k = 0; k < KBINS; ++k) {
        float d = g_sig[(2 * t) * KBINS + k] - g_sig[(2 * t + 1) * KBINS + k];
        v += d * d;
    }
    v *= (1.f / (float)KBINS);   // mean over K
    red[t] = v;
    __syncthreads();
    for (int s = 64; s > 0; s >>= 1) {
        if (t < s) red[t] += red[t + s];
        __syncthreads();
    }
    float result = 0.1f * (red[0] * (1.f / 128.f) + g_ntx);   // LAMBDA = 0.1
    for (int i = t; i < out_size; i += 128) out[i] = result;
}

extern "C" void kernel_launch(void* const* d_in, const int* in_sizes, int n_in,
                              void* d_out, int out_size)
{
    // metadata order: H1, batch1, H2, batch2, z1, z2 (batch arrays unused: equal-size graphs)
    const float* H1 = (const float*)d_in[0];
    const float* H2 = (const float*)d_in[2];
    const float* Z1 = (const float*)d_in[4];
    const float* Z2 = (const float*)d_in[5];

    cudaFuncSetAttribute(k_main, cudaFuncAttributeMaxDynamicSharedMemorySize, SMEM_BYTES);

    k_main<<<NGV + 1, 256, SMEM_BYTES>>>(H1, H2, Z1, Z2);
    k_final<<<1, 128>>>((float*)d_out, out_size);
}